// round 10
// baseline (speedup 1.0000x reference)
#include <cuda_runtime.h>

// ScorePredictor: 3x DistMult edge scoring.
// score[e] = clip( sum_d head[src[e],d] * rel[d] * tail[dst[e],d], 0, 1 )
//
// Structure: 3 parallel streams (fork/join via events, graph-capturable),
// one per edge list. Each stream: counting sort by one endpoint
// (zero/hist/scan/scatter -> packed int4 records) then the score kernel.
// The per-phase sorts (~9us) are off the critical path of the other phases,
// so the chip reaches LTS saturation almost immediately.
//
// Score kernel (the R7/R9 winner): each warp handles 8 consecutive SORTED
// edges, k-chunk outer loop; rel chunk loaded once per k, head chunk
// (pre-multiplied by rel) reloaded only on key change, all 8 independent
// tail loads batched before the FMAs (MLP=8/warp). EPW=8 fits the register
// budget at __launch_bounds__(256,3); EPW=16 spilled and regressed 30%.

#define D_DIM 2048
#define WARPS_PER_BLOCK 8
#define THREADS_PER_BLOCK (WARPS_PER_BLOCK * 32)
#define EDGES_PER_WARP 8
#define EDGES_PER_BLOCK (WARPS_PER_BLOCK * EDGES_PER_WARP)

#define MAX_BINS 32768
#define MAX_E    131072

__device__ int  g_hist[3][MAX_BINS];
__device__ int4 g_edge[3][MAX_E];    // (key, other, edge, pad)

// ---------------- per-phase sort: zero / hist / scan / scatter ----------------

template <int P>
__global__ void zero_hist_p(int nbins) {
    int i = blockIdx.x * blockDim.x + threadIdx.x;
    if (i < nbins) g_hist[P][i] = 0;
}

template <int P>
__global__ void hist_p(const int* __restrict__ key, int E) {
    int i = blockIdx.x * blockDim.x + threadIdx.x;
    if (i < E) atomicAdd(&g_hist[P][__ldg(key + i)], 1);
}

template <int P>
__global__ void scan_p(int nbins) {
    int* h = g_hist[P];
    const int T = 1024;
    const int t = threadIdx.x;
    __shared__ int buf[2][1024];

    int chunk = (nbins + T - 1) / T;
    int start = t * chunk;
    int end   = min(start + chunk, nbins);

    int s = 0;
    for (int i = start; i < end; ++i) s += h[i];
    buf[0][t] = s;
    __syncthreads();

    int src = 0;
    for (int off = 1; off < T; off <<= 1) {
        int v = buf[src][t];
        if (t >= off) v += buf[src][t - off];
        buf[src ^ 1][t] = v;
        src ^= 1;
        __syncthreads();
    }

    int base = (t == 0) ? 0 : buf[src][t - 1];
    int run = base;
    for (int i = start; i < end; ++i) {
        int v = h[i];
        h[i] = run;
        run += v;
    }
}

template <int P>
__global__ void scatter_p(const int* __restrict__ key,
                          const int* __restrict__ other, int E) {
    int i = blockIdx.x * blockDim.x + threadIdx.x;
    if (i >= E) return;
    int k = __ldg(key + i);
    int o = __ldg(other + i);
    int pos = atomicAdd(&g_hist[P][k], 1);
    g_edge[P][pos] = make_int4(k, o, i, 0);
}

// ---------------- score ----------------

template <int P>
__global__ __launch_bounds__(THREADS_PER_BLOCK, 3)
void score_p(
    const float* __restrict__ xs,    // sorted-side table (heads)
    const float* __restrict__ xr,    // random-side table (tails)
    const float* __restrict__ rel,
    float*       __restrict__ o,
    int E)
{
    const int4* recs = g_edge[P];

    const int warp = threadIdx.x >> 5;
    const int lane = threadIdx.x & 31;
    const int base = (blockIdx.x * WARPS_PER_BLOCK + warp) * EDGES_PER_WARP;
    if (base >= E) return;

    // Lanes 0..7 fetch packed edge records; broadcast via shuffles.
    int pos = base + lane;
    if (pos >= E) pos = E - 1;              // duplicate last edge (same output)
    int my_s = 0, my_d = 0, my_edge = 0;
    if (lane < EDGES_PER_WARP) {
        int4 r = __ldg(recs + pos);
        my_s = r.x; my_d = r.y; my_edge = r.z;
    }

    int s[EDGES_PER_WARP], dI[EDGES_PER_WARP];
    #pragma unroll
    for (int e = 0; e < EDGES_PER_WARP; ++e) {
        s[e]  = __shfl_sync(0xffffffffu, my_s, e);
        dI[e] = __shfl_sync(0xffffffffu, my_d, e);
    }

    float acc[EDGES_PER_WARP];
    #pragma unroll
    for (int e = 0; e < EDGES_PER_WARP; ++e) acc[e] = 0.0f;

    // 16 k-chunks of float4 per lane. Batch all 8 independent tail loads
    // before the FMA block so ptxas issues them back-to-back (MLP=8).
    #pragma unroll 2
    for (int k = 0; k < D_DIM / (32 * 4); ++k) {
        const int idx = (k * 32 + lane) * 4;

        float4 t[EDGES_PER_WARP];
        #pragma unroll
        for (int e = 0; e < EDGES_PER_WARP; ++e)
            t[e] = __ldg(reinterpret_cast<const float4*>(
                       xr + (size_t)dI[e] * D_DIM + idx));

        const float4 r = __ldg(reinterpret_cast<const float4*>(rel + idx));

        float4 hr;   // head chunk pre-multiplied by rel; reload on key change
        #pragma unroll
        for (int e = 0; e < EDGES_PER_WARP; ++e) {
            if (e == 0 || s[e] != s[e - 1]) {   // warp-uniform branch
                float4 h = __ldg(reinterpret_cast<const float4*>(
                               xs + (size_t)s[e] * D_DIM + idx));
                hr.x = h.x * r.x; hr.y = h.y * r.y;
                hr.z = h.z * r.z; hr.w = h.w * r.w;
            }
            acc[e] = fmaf(hr.x, t[e].x, acc[e]);
            acc[e] = fmaf(hr.y, t[e].y, acc[e]);
            acc[e] = fmaf(hr.z, t[e].z, acc[e]);
            acc[e] = fmaf(hr.w, t[e].w, acc[e]);
        }
    }

    // Reduce and write each edge's score.
    #pragma unroll
    for (int e = 0; e < EDGES_PER_WARP; ++e) {
        float a = acc[e];
        #pragma unroll
        for (int off = 16; off > 0; off >>= 1)
            a += __shfl_xor_sync(0xffffffffu, a, off);
        const int edge_e = __shfl_sync(0xffffffffu, my_edge, e);
        if (lane == 0)
            o[edge_e] = fminf(fmaxf(a, 0.0f), 1.0f);
    }
}

// ---------------- launch ----------------

static cudaStream_t g_st[3];
static cudaEvent_t  g_fork, g_done[3];

static bool g_init_streams() {
    for (int i = 0; i < 3; ++i)
        cudaStreamCreateWithFlags(&g_st[i], cudaStreamNonBlocking);
    cudaEventCreateWithFlags(&g_fork, cudaEventDisableTiming);
    for (int i = 0; i < 3; ++i)
        cudaEventCreateWithFlags(&g_done[i], cudaEventDisableTiming);
    return true;
}

template <int P>
static void run_phase(cudaStream_t st,
                      const int* key, const int* other,
                      const float* xs, const float* xr, const float* rel,
                      float* o, int E, int nbins)
{
    zero_hist_p<P><<<(nbins + 255) / 256, 256, 0, st>>>(nbins);
    hist_p<P><<<(E + 255) / 256, 256, 0, st>>>(key, E);
    scan_p<P><<<1, 1024, 0, st>>>(nbins);
    scatter_p<P><<<(E + 255) / 256, 256, 0, st>>>(key, other, E);
    const int bpp = (E + EDGES_PER_BLOCK - 1) / EDGES_PER_BLOCK;
    score_p<P><<<bpp, THREADS_PER_BLOCK, 0, st>>>(xs, xr, rel, o, E);
}

extern "C" void kernel_launch(void* const* d_in, const int* in_sizes, int n_in,
                              void* d_out, int out_size)
{
    // Created once on the (uncaptured) correctness call; reused during capture.
    static bool inited = g_init_streams();
    (void)inited;

    const float* x_drug  = (const float*)d_in[0];
    const float* x_prot  = (const float*)d_in[1];
    const float* rel_ddi = (const float*)d_in[2];
    const float* rel_dpi = (const float*)d_in[3];
    const int*   ddi_src = (const int*)d_in[4];
    const int*   ddi_dst = (const int*)d_in[5];
    const int*   dpi_src = (const int*)d_in[6];
    const int*   dpi_dst = (const int*)d_in[7];
    const int*   ppi_src = (const int*)d_in[8];
    const int*   ppi_dst = (const int*)d_in[9];
    float* out = (float*)d_out;

    const int E      = in_sizes[4];
    const int N_DRUG = in_sizes[0] / D_DIM;
    const int N_PROT = in_sizes[1] / D_DIM;

    // Fork: all three per-phase pipelines branch off the calling stream.
    cudaEventRecord(g_fork, 0);
    for (int i = 0; i < 3; ++i)
        cudaStreamWaitEvent(g_st[i], g_fork, 0);

    // Phase 0: ddi — sort by src (drug).
    run_phase<0>(g_st[0], ddi_src, ddi_dst,
                 x_drug, x_drug, rel_ddi, out, E, N_DRUG);
    // Phase 1: dpi — sort by dst (protein side is the head table).
    run_phase<1>(g_st[1], dpi_dst, dpi_src,
                 x_prot, x_drug, rel_dpi, out + E, E, N_PROT);
    // Phase 2: ppi — sort by src (protein).
    run_phase<2>(g_st[2], ppi_src, ppi_dst,
                 x_prot, x_prot, rel_dpi, out + 2 * E, E, N_PROT);

    // Join back into the calling stream.
    for (int i = 0; i < 3; ++i) {
        cudaEventRecord(g_done[i], g_st[i]);
        cudaStreamWaitEvent(0, g_done[i], 0);
    }
}